// round 4
// baseline (speedup 1.0000x reference)
#include <cuda_runtime.h>

#define B_  8
#define C_  256
#define H_  128
#define W_  128
#define HW  16384
#define NHD 16
#define DH  16

// ---------------- scratch: lifetime-aliased static buffers (768 MB total) ----
// bufA: pre (stages 1-2), then mix (stages 5-6)
// bufB: loc (stages 2-5)
// bufC: qkv (stages 3-4), then dwo (stages 6-7)  [needs 384 MB for qkv]
// bufD: att (stages 4-5)
__device__ float g_bufA[(size_t)B_ * C_ * HW];
__device__ float g_bufB[(size_t)B_ * C_ * HW];
__device__ float g_bufC[(size_t)B_ * 768 * HW];
__device__ float g_bufD[(size_t)B_ * C_ * HW];

// =============================================================================
// 1x1 conv (Cin=256) as per-batch SGEMM: out[b,co,p] = sum_ci W[co,ci]*in[b,ci,p]
// 128x128 block tile, K-step 8, 8x8 microtile per thread. Optional fused BN.
// grid: (HW/128, Cout/128, B), block 256
// =============================================================================
__global__ __launch_bounds__(256, 2) void conv1x1_kernel(
    const float* __restrict__ in, const float* __restrict__ Wt,
    const float* __restrict__ bnp, float* __restrict__ out,
    int Cout, int use_bn)
{
    __shared__ float As[8][132];
    __shared__ float Bs[8][132];
    const int b   = blockIdx.z;
    const int m0  = blockIdx.y * 128;
    const int n0  = blockIdx.x * 128;
    const int tid = threadIdx.x;
    const int tm  = tid >> 4, tn = tid & 15;

    const float* inB = in + (size_t)b * C_ * HW + n0;

    float acc[8][8];
#pragma unroll
    for (int i = 0; i < 8; i++)
#pragma unroll
        for (int j = 0; j < 8; j++) acc[i][j] = 0.f;

    const int am  = tid >> 1;         // 0..127  (M row for A load)
    const int ak  = (tid & 1) * 4;    // 0 or 4  (K quad for A load)
    const int bk  = tid >> 5;         // 0..7    (K row for B load)
    const int bn4 = (tid & 31) * 4;   // 0..124  (N quad for B load)

    for (int kk = 0; kk < 256; kk += 8) {
        float4 av = *(const float4*)&Wt[(size_t)(m0 + am) * 256 + kk + ak];
        As[ak + 0][am] = av.x; As[ak + 1][am] = av.y;
        As[ak + 2][am] = av.z; As[ak + 3][am] = av.w;
        float4 bv = *(const float4*)&inB[(size_t)(kk + bk) * HW + bn4];
        *(float4*)&Bs[bk][bn4] = bv;
        __syncthreads();
#pragma unroll
        for (int k = 0; k < 8; k++) {
            float a[8], bb[8];
            *(float4*)&a[0]  = *(const float4*)&As[k][tm * 8];
            *(float4*)&a[4]  = *(const float4*)&As[k][tm * 8 + 4];
            *(float4*)&bb[0] = *(const float4*)&Bs[k][tn * 8];
            *(float4*)&bb[4] = *(const float4*)&Bs[k][tn * 8 + 4];
#pragma unroll
            for (int i = 0; i < 8; i++)
#pragma unroll
                for (int j = 0; j < 8; j++)
                    acc[i][j] = fmaf(a[i], bb[j], acc[i][j]);
        }
        __syncthreads();
    }

#pragma unroll
    for (int i = 0; i < 8; i++) {
        const int co = m0 + tm * 8 + i;
        float scale = 1.f, shift = 0.f;
        if (use_bn) {
            float g  = bnp[co],            be = bnp[Cout + co];
            float mu = bnp[2 * Cout + co], va = bnp[3 * Cout + co];
            scale = g * rsqrtf(va + 1e-5f);
            shift = be - mu * scale;
        }
        float* o = out + (size_t)b * Cout * HW + (size_t)co * HW + n0 + tn * 8;
        float r[8];
#pragma unroll
        for (int j = 0; j < 8; j++) r[j] = acc[i][j] * scale + shift;
        *(float4*)&o[0] = *(float4*)&r[0];
        *(float4*)&o[4] = *(float4*)&r[4];
    }
}

// =============================================================================
// Dilated 3x3 conv on a channel group as implicit GEMM.
// K = Cg*9 with k = ci*9 + tap (tap = ky*3+kx).  One block = one full image row
// (N=128) x up to 128 output channels (Cg<=86 -> single M tile with guards).
// grid: (H, 1, B), block 256.  Fused BN.  Zero padding at image borders.
// =============================================================================
__global__ __launch_bounds__(256, 2) void dilconv_kernel(
    const float* __restrict__ in,   // base already offset by cin_off*HW
    const float* __restrict__ Wt,   // (Cg, Cg, 3, 3) row-major
    const float* __restrict__ bnp,  // (4, Cg)
    float* __restrict__ out,        // base already offset by co_off*HW
    int Cg, int dil)
{
    __shared__ float As[8][132];
    __shared__ float Bs[8][132];
    const int b   = blockIdx.z;
    const int h   = blockIdx.x;     // image row; block covers all 128 columns
    const int tid = threadIdx.x;
    const int tm  = tid >> 4, tn = tid & 15;
    const int K   = Cg * 9;

    const float* inB = in + (size_t)b * C_ * HW;

    float acc[8][8];
#pragma unroll
    for (int i = 0; i < 8; i++)
#pragma unroll
        for (int j = 0; j < 8; j++) acc[i][j] = 0.f;

    const int am  = tid >> 1;
    const int ak  = (tid & 1) * 4;
    const int bk  = tid >> 5;
    const int bn4 = (tid & 31) * 4;

    for (int kk = 0; kk < K; kk += 8) {
        // A tile: weights, zero-padded beyond Cg/K
#pragma unroll
        for (int j = 0; j < 4; j++) {
            const int kg = kk + ak + j;
            float aval = 0.f;
            if (am < Cg && kg < K) aval = Wt[(size_t)am * K + kg];
            As[ak + j][am] = aval;
        }
        // B tile: shifted input row with zero padding at image borders
        {
            const int kg = kk + bk;
            float v0 = 0.f, v1 = 0.f, v2 = 0.f, v3 = 0.f;
            if (kg < K) {
                const int ci  = kg / 9;
                const int tap = kg - ci * 9;
                const int dy  = tap / 3 - 1;
                const int dx  = tap - (tap / 3) * 3 - 1;
                const int sh  = h + dy * dil;
                if (sh >= 0 && sh < H_) {
                    const float* row = inB + (size_t)ci * HW + sh * W_;
                    const int s0 = bn4 + dx * dil;
                    if (s0     >= 0 && s0     < W_) v0 = row[s0];
                    if (s0 + 1 >= 0 && s0 + 1 < W_) v1 = row[s0 + 1];
                    if (s0 + 2 >= 0 && s0 + 2 < W_) v2 = row[s0 + 2];
                    if (s0 + 3 >= 0 && s0 + 3 < W_) v3 = row[s0 + 3];
                }
            }
            Bs[bk][bn4 + 0] = v0; Bs[bk][bn4 + 1] = v1;
            Bs[bk][bn4 + 2] = v2; Bs[bk][bn4 + 3] = v3;
        }
        __syncthreads();
#pragma unroll
        for (int k = 0; k < 8; k++) {
            float a[8], bb[8];
            *(float4*)&a[0]  = *(const float4*)&As[k][tm * 8];
            *(float4*)&a[4]  = *(const float4*)&As[k][tm * 8 + 4];
            *(float4*)&bb[0] = *(const float4*)&Bs[k][tn * 8];
            *(float4*)&bb[4] = *(const float4*)&Bs[k][tn * 8 + 4];
#pragma unroll
            for (int i = 0; i < 8; i++)
#pragma unroll
                for (int j = 0; j < 8; j++)
                    acc[i][j] = fmaf(a[i], bb[j], acc[i][j]);
        }
        __syncthreads();
    }

#pragma unroll
    for (int i = 0; i < 8; i++) {
        const int co = tm * 8 + i;
        if (co < Cg) {
            float g  = bnp[co],          be = bnp[Cg + co];
            float mu = bnp[2 * Cg + co], va = bnp[3 * Cg + co];
            float scale = g * rsqrtf(va + 1e-5f);
            float shift = be - mu * scale;
            float* o = out + (size_t)b * C_ * HW + (size_t)co * HW + h * W_ + tn * 8;
            float r[8];
#pragma unroll
            for (int j = 0; j < 8; j++) r[j] = acc[i][j] * scale + shift;
            *(float4*)&o[0] = *(float4*)&r[0];
            *(float4*)&o[4] = *(float4*)&r[4];
        }
    }
}

// =============================================================================
// Windowed attention: one block = (window, head). 64 threads, thread i = token i.
// dots -> +bias -> softmax -> @V, scores kept in registers (loops fully unrolled).
// grid: (B*16*16, NH), block 64
// =============================================================================
__global__ __launch_bounds__(64) void attn_kernel(
    const float* __restrict__ qkv, const float* __restrict__ rpb,
    float* __restrict__ out)
{
    const int win  = blockIdx.x;           // b*256 + wy*16 + wx
    const int head = blockIdx.y;
    const int b    = win >> 8;
    const int wy   = (win >> 4) & 15;
    const int wx   = win & 15;
    const int i    = threadIdx.x;          // token 0..63
    const int yi   = i >> 3, xi = i & 7;
    const int py   = wy * 8 + yi, px = wx * 8 + xi;

    __shared__ float ks[64][16];
    __shared__ float vs[64][16];
    __shared__ float bias_s[232];

    const size_t pix = (size_t)py * W_ + px;
    const float* qb  = qkv + ((size_t)b * 768 + head * DH) * HW + pix;

    float q[16];
#pragma unroll
    for (int dd = 0; dd < 16; dd++) {
        q[dd]     = qb[(size_t)dd * HW];
        ks[i][dd] = qb[(size_t)(256 + dd) * HW];
        vs[i][dd] = qb[(size_t)(512 + dd) * HW];
    }
    for (int t = i; t < 225; t += 64) bias_s[t] = rpb[t * NHD + head];
    __syncthreads();

    float s[64];
    float mx = -1e30f;
#pragma unroll
    for (int j = 0; j < 64; j++) {
        const float4* kr = (const float4*)&ks[j][0];
        float4 k0 = kr[0], k1 = kr[1], k2 = kr[2], k3 = kr[3];
        float dot = q[0]  * k0.x + q[1]  * k0.y + q[2]  * k0.z + q[3]  * k0.w
                  + q[4]  * k1.x + q[5]  * k1.y + q[6]  * k1.z + q[7]  * k1.w
                  + q[8]  * k2.x + q[9]  * k2.y + q[10] * k2.z + q[11] * k2.w
                  + q[12] * k3.x + q[13] * k3.y + q[14] * k3.z + q[15] * k3.w;
        const int yj = j >> 3, xj = j & 7;
        float val = dot * 0.25f + bias_s[(yi - yj + 7) * 15 + (xi - xj + 7)];
        s[j] = val;
        mx = fmaxf(mx, val);
    }
    float sum = 0.f;
#pragma unroll
    for (int j = 0; j < 64; j++) { float e = __expf(s[j] - mx); s[j] = e; sum += e; }
    const float inv = 1.f / sum;

    float4 o0 = {0, 0, 0, 0}, o1 = o0, o2 = o0, o3 = o0;
#pragma unroll
    for (int j = 0; j < 64; j++) {
        const float p = s[j];
        const float4* vr = (const float4*)&vs[j][0];
        float4 v0 = vr[0], v1 = vr[1], v2 = vr[2], v3 = vr[3];
        o0.x += p * v0.x; o0.y += p * v0.y; o0.z += p * v0.z; o0.w += p * v0.w;
        o1.x += p * v1.x; o1.y += p * v1.y; o1.z += p * v1.z; o1.w += p * v1.w;
        o2.x += p * v2.x; o2.y += p * v2.y; o2.z += p * v2.z; o2.w += p * v2.w;
        o3.x += p * v3.x; o3.y += p * v3.y; o3.z += p * v3.z; o3.w += p * v3.w;
    }

    float ov[16] = {o0.x, o0.y, o0.z, o0.w, o1.x, o1.y, o1.z, o1.w,
                    o2.x, o2.y, o2.z, o2.w, o3.x, o3.y, o3.z, o3.w};
    float* ob = out + ((size_t)b * C_ + head * DH) * HW + pix;
#pragma unroll
    for (int dd = 0; dd < 16; dd++) ob[(size_t)dd * HW] = ov[dd] * inv;
}

// =============================================================================
// ax + ay + local.  ax[h] = 1/8 * sum_{r=h-3..h+4} P(r,w) with P(128)=att(126),
// zero outside [0,128]; ay symmetric along w.
// =============================================================================
__global__ __launch_bounds__(256) void pooladd_kernel(
    const float* __restrict__ att, const float* __restrict__ loc,
    float* __restrict__ out)
{
    const size_t idx = (size_t)blockIdx.x * 256 + threadIdx.x;
    const int w = (int)(idx & (W_ - 1));
    const int h = (int)((idx >> 7) & (H_ - 1));
    const size_t bc = idx >> 14;
    const float* p = att + (bc << 14);
    float sx = 0.f, sy = 0.f;
#pragma unroll
    for (int t = -3; t <= 4; t++) {
        const int r = h + t;
        if (r >= 0 && r <= H_) { const int rr = (r == H_) ? H_ - 2 : r; sx += p[rr * W_ + w]; }
        const int c2 = w + t;
        if (c2 >= 0 && c2 <= W_) { const int cc = (c2 == W_) ? W_ - 2 : c2; sy += p[h * W_ + cc]; }
    }
    out[idx] = (sx + sy) * 0.125f + loc[idx];
}

// =============================================================================
// Depthwise 8x8 conv on reflect-(0,1)-padded input, conv pad=3.
// out[h,w] = sum_{u,v} w[c,u,v] * P(h+u-3, w+v-3); P index range [0,128],
// P(128)=in(126), zero outside.  grid: (8, 8, B*C), block 16x16
// =============================================================================
__global__ __launch_bounds__(256) void dw_kernel(
    const float* __restrict__ in, const float* __restrict__ wdw,
    float* __restrict__ out)
{
    __shared__ float tile[23][48];
    __shared__ float wt[64];
    const int bc = blockIdx.z;
    const int h0 = blockIdx.y * 16, w0 = blockIdx.x * 16;
    const int tx = threadIdx.x, ty = threadIdx.y;
    const int tid = ty * 16 + tx;
    const float* p = in + (size_t)bc * HW;

    if (tid < 64) wt[tid] = wdw[(size_t)(bc & 255) * 64 + tid];
    for (int t = tid; t < 23 * 23; t += 256) {
        const int r = h0 - 3 + t / 23;
        const int s = w0 - 3 + t % 23;
        float v = 0.f;
        if (r >= 0 && r <= H_ && s >= 0 && s <= W_) {
            const int rr = (r == H_) ? H_ - 2 : r;
            const int ss = (s == W_) ? W_ - 2 : s;
            v = p[rr * W_ + ss];
        }
        tile[t / 23][t % 23] = v;
    }
    __syncthreads();

    float acc = 0.f;
#pragma unroll
    for (int u = 0; u < 8; u++)
#pragma unroll
        for (int v = 0; v < 8; v++)
            acc = fmaf(wt[u * 8 + v], tile[ty + u][tx + v], acc);
    out[(size_t)bc * HW + (h0 + ty) * W_ + w0 + tx] = acc;
}

// =============================================================================
extern "C" void kernel_launch(void* const* d_in, const int* in_sizes, int n_in,
                              void* d_out, int out_size)
{
    const float* x       = (const float*)d_in[0];
    const float* w_pre   = (const float*)d_in[1];
    const float* bn_pre  = (const float*)d_in[2];
    const float* w_l1    = (const float*)d_in[3];
    const float* bn_l1   = (const float*)d_in[4];
    const float* w_l2    = (const float*)d_in[5];
    const float* bn_l2   = (const float*)d_in[6];
    const float* w_l3    = (const float*)d_in[7];
    const float* bn_l3   = (const float*)d_in[8];
    const float* w_qkv   = (const float*)d_in[9];
    const float* rpb     = (const float*)d_in[10];
    const float* w_dw    = (const float*)d_in[11];
    const float* w_pw    = (const float*)d_in[12];
    const float* bn_proj = (const float*)d_in[13];
    float* out = (float*)d_out;

    float *bufA, *bufB, *bufC, *bufD;
    cudaGetSymbolAddress((void**)&bufA, g_bufA);
    cudaGetSymbolAddress((void**)&bufB, g_bufB);
    cudaGetSymbolAddress((void**)&bufC, g_bufC);
    cudaGetSymbolAddress((void**)&bufD, g_bufD);

    float* pre  = bufA;   // stages 1-2
    float* loc  = bufB;   // stages 2-5
    float* qkvb = bufC;   // stages 3-4
    float* att  = bufD;   // stages 4-5
    float* mix  = bufA;   // stages 5-6 (pre dead)
    float* dwo  = bufC;   // stages 6-7 (qkv dead)

    // 1. pre 1x1 + BN
    conv1x1_kernel<<<dim3(HW / 128, 2, B_), 256>>>(x, w_pre, bn_pre, pre, 256, 1);
    // 2. dilated 3x3 group convs + BN (concat layout written in place)
    dilconv_kernel<<<dim3(H_, 1, B_), 256>>>(pre,            w_l1, bn_l1, loc,            86, 1);
    dilconv_kernel<<<dim3(H_, 1, B_), 256>>>(pre +  86 * HW, w_l2, bn_l2, loc +  86 * HW, 86, 2);
    dilconv_kernel<<<dim3(H_, 1, B_), 256>>>(pre + 172 * HW, w_l3, bn_l3, loc + 172 * HW, 84, 3);
    // 3. qkv 1x1 (no BN)
    conv1x1_kernel<<<dim3(HW / 128, 6, B_), 256>>>(x, w_qkv, w_qkv, qkvb, 768, 0);
    // 4. windowed attention
    attn_kernel<<<dim3(B_ * 16 * 16, NHD), 64>>>(qkvb, rpb, att);
    // 5. ax + ay + local
    pooladd_kernel<<<dim3((unsigned)((size_t)B_ * C_ * HW / 256)), 256>>>(att, loc, mix);
    // 6. depthwise 8x8
    dw_kernel<<<dim3(8, 8, B_ * C_), dim3(16, 16)>>>(mix, w_dw, dwo);
    // 7. pw 1x1 + BN -> final output
    conv1x1_kernel<<<dim3(HW / 128, 2, B_), 256>>>(dwo, w_pw, bn_proj, out, 256, 1);
}

// round 6
// speedup vs baseline: 1.8995x; 1.8995x over previous
#include <cuda_runtime.h>
#include <cuda_bf16.h>

typedef unsigned int u32;

#define B_  8
#define C_  256
#define H_  128
#define W_  128
#define HW  16384
#define NHD 16
#define DH  16

// ---------------- fp32 stage buffers (lifetime-aliased) ----------------------
__device__ float g_bufA[(size_t)B_ * C_ * HW];   // pre out  -> mix
__device__ float g_bufB[(size_t)B_ * C_ * HW];   // loc
__device__ float g_bufC[(size_t)B_ * 768 * HW];  // qkv out  -> dwo
__device__ float g_bufD[(size_t)B_ * C_ * HW];   // att

// ---------------- packed bf16 hi/lo activations [B][128 pair-rows][HW] -------
// g_pHi/g_pLo are reused for the dwo pack (stage 7) — disjoint lifetimes.
#define APACK ((size_t)B_ * 128 * HW)
__device__ u32 g_xHi[APACK], g_xLo[APACK];   // from x       (pre + qkv input)
__device__ u32 g_pHi[APACK], g_pLo[APACK];   // from pre out (dil input), then dwo (pw input)

// ---------------- packed bf16 hi/lo weights ----------------------------------
// 1x1:  [K/2=128][M]   pairs along K packed in u32 (low 16 = even channel)
__device__ u32 g_wPreHi[128 * 256], g_wPreLo[128 * 256];
__device__ u32 g_wQkvHi[128 * 768], g_wQkvLo[128 * 768];
__device__ u32 g_wPwHi [128 * 256], g_wPwLo [128 * 256];
// dil:  [group][tap 9][pair-row 48][m 96]
__device__ u32 g_wDilHi[3 * 9 * 48 * 96], g_wDilLo[3 * 9 * 48 * 96];

// ---------------- bf16 split helpers -----------------------------------------
__device__ __forceinline__ u32 split_pack(float x0, float x1, u32& lo) {
    __nv_bfloat16 h0 = __float2bfloat16(x0);
    __nv_bfloat16 h1 = __float2bfloat16(x1);
    __nv_bfloat16 l0 = __float2bfloat16(x0 - __bfloat162float(h0));
    __nv_bfloat16 l1 = __float2bfloat16(x1 - __bfloat162float(h1));
    lo = (u32)__bfloat16_as_ushort(l0) | ((u32)__bfloat16_as_ushort(l1) << 16);
    return (u32)__bfloat16_as_ushort(h0) | ((u32)__bfloat16_as_ushort(h1) << 16);
}

// ---------------- activation pack: fp32 [B][256][HW] -> hi/lo [B][128][HW] ---
__global__ __launch_bounds__(256) void pack_act(
    const float* __restrict__ in, u32* __restrict__ hi, u32* __restrict__ lo)
{
    const size_t idx = (size_t)blockIdx.x * 256 + threadIdx.x; // B*128*(HW/4)
    const size_t p4  = idx & 4095;
    const size_t t   = idx >> 12;              // b*128 + c2
    const int    c2  = (int)(t & 127);
    const int    b   = (int)(t >> 7);
    const float* r0  = in + ((size_t)b * C_ + 2 * c2) * HW + p4 * 4;
    float4 a = *(const float4*)r0;
    float4 c = *(const float4*)(r0 + HW);
    u32 hv[4], lv[4];
    hv[0] = split_pack(a.x, c.x, lv[0]);
    hv[1] = split_pack(a.y, c.y, lv[1]);
    hv[2] = split_pack(a.z, c.z, lv[2]);
    hv[3] = split_pack(a.w, c.w, lv[3]);
    *(uint4*)(hi + t * HW + p4 * 4) = make_uint4(hv[0], hv[1], hv[2], hv[3]);
    *(uint4*)(lo + t * HW + p4 * 4) = make_uint4(lv[0], lv[1], lv[2], lv[3]);
}

// ---------------- 1x1 weight pack: W[M][256] -> [128][M] pair-packed ---------
__global__ __launch_bounds__(256) void pack_w1x1(
    const float* __restrict__ W, u32* __restrict__ hi, u32* __restrict__ lo, int M)
{
    const int idx = blockIdx.x * 256 + threadIdx.x;
    if (idx >= M * 128) return;
    const int m = idx % M, k2 = idx / M;
    u32 l;
    u32 h = split_pack(W[m * 256 + 2 * k2], W[m * 256 + 2 * k2 + 1], l);
    hi[(size_t)k2 * M + m] = h;
    lo[(size_t)k2 * M + m] = l;
}

// ---------------- dil weight pack: W[Cg][Cg][3][3] -> [9][48][96] ------------
__global__ __launch_bounds__(256) void pack_wdil(
    const float* __restrict__ W, u32* __restrict__ hi, u32* __restrict__ lo, int Cg)
{
    const int idx = blockIdx.x * 256 + threadIdx.x;
    if (idx >= 9 * 48 * 96) return;
    const int m  = idx % 96;
    const int r  = idx / 96;
    const int k2 = r % 48;
    const int t  = r / 48;
    float a = 0.f, b = 0.f;
    if (m < Cg) {
        if (2 * k2     < Cg) a = W[((size_t)m * Cg + 2 * k2)     * 9 + t];
        if (2 * k2 + 1 < Cg) b = W[((size_t)m * Cg + 2 * k2 + 1) * 9 + t];
    }
    u32 l;
    u32 h = split_pack(a, b, l);
    hi[idx] = h;  lo[idx] = l;
}

// ---------------- mma.m16n8k16 bf16 wrapper ----------------------------------
__device__ __forceinline__ void mma16816(float* d, const u32* a, const u32* b) {
    asm volatile(
        "mma.sync.aligned.m16n8k16.row.col.f32.bf16.bf16.f32 "
        "{%0,%1,%2,%3}, {%4,%5,%6,%7}, {%8,%9}, {%0,%1,%2,%3};"
        : "+f"(d[0]), "+f"(d[1]), "+f"(d[2]), "+f"(d[3])
        : "r"(a[0]), "r"(a[1]), "r"(a[2]), "r"(a[3]), "r"(b[0]), "r"(b[1]));
}

// =============================================================================
// 1x1 conv GEMM (K=256), bf16x3.  Block: 128M x 128N, 8 warps, warp 64x32.
// grid: (HW/128, Mtot/128, B), block 256.
// =============================================================================
__global__ __launch_bounds__(256) void gemm1x1_mma(
    const u32* __restrict__ wHi, const u32* __restrict__ wLo, int Mtot,
    const u32* __restrict__ aHi, const u32* __restrict__ aLo,
    float* __restrict__ out, const float* __restrict__ bnp, int Cout, int use_bn)
{
    __shared__ u32 AsH[8][136], AsL[8][136], BsH[8][136], BsL[8][136];
    const int b    = blockIdx.z;
    const int m0   = blockIdx.y * 128, n0 = blockIdx.x * 128;
    const int tid  = threadIdx.x, wid = tid >> 5, lane = tid & 31;
    const int wm   = (wid >> 2) * 64, wn = (wid & 3) * 32;
    const int g    = lane >> 2, q = lane & 3;
    const u32* aHiB = aHi + (size_t)b * 128 * HW + n0;
    const u32* aLoB = aLo + (size_t)b * 128 * HW + n0;

    float acc[4][4][4];
#pragma unroll
    for (int i = 0; i < 4; i++)
#pragma unroll
        for (int j = 0; j < 4; j++)
#pragma unroll
            for (int r = 0; r < 4; r++) acc[i][j][r] = 0.f;

    for (int kk = 0; kk < 16; kk++) {
        __syncthreads();
#pragma unroll
        for (int qd = 0; qd < 4; qd++) {
            const int idx = tid + qd * 256;
            const int k2 = idx >> 7, m = idx & 127;
            const size_t wo = (size_t)(kk * 8 + k2) * Mtot + m0 + m;
            AsH[k2][m] = wHi[wo];  AsL[k2][m] = wLo[wo];
            const size_t ao = (size_t)(kk * 8 + k2) * HW + m;
            BsH[k2][m] = aHiB[ao]; BsL[k2][m] = aLoB[ao];
        }
        __syncthreads();

        u32 aH[4][4], aL[4][4], bH[4][2], bL[4][2];
#pragma unroll
        for (int i = 0; i < 4; i++) {
            const int base = wm + i * 16 + g;
            aH[i][0] = AsH[q][base];     aH[i][1] = AsH[q][base + 8];
            aH[i][2] = AsH[q + 4][base]; aH[i][3] = AsH[q + 4][base + 8];
            aL[i][0] = AsL[q][base];     aL[i][1] = AsL[q][base + 8];
            aL[i][2] = AsL[q + 4][base]; aL[i][3] = AsL[q + 4][base + 8];
        }
#pragma unroll
        for (int j = 0; j < 4; j++) {
            const int nb = wn + j * 8 + g;
            bH[j][0] = BsH[q][nb]; bH[j][1] = BsH[q + 4][nb];
            bL[j][0] = BsL[q][nb]; bL[j][1] = BsL[q + 4][nb];
        }
#pragma unroll
        for (int i = 0; i < 4; i++)
#pragma unroll
            for (int j = 0; j < 4; j++) {
                mma16816(acc[i][j], aH[i], bH[j]);
                mma16816(acc[i][j], aH[i], bL[j]);
                mma16816(acc[i][j], aL[i], bH[j]);
            }
    }

#pragma unroll
    for (int i = 0; i < 4; i++)
#pragma unroll
        for (int half = 0; half < 2; half++) {
            const int co = m0 + wm + i * 16 + g + half * 8;
            float scale = 1.f, shift = 0.f;
            if (use_bn) {
                const float gg = bnp[co],            be = bnp[Cout + co];
                const float mu = bnp[2 * Cout + co], va = bnp[3 * Cout + co];
                scale = gg * rsqrtf(va + 1e-5f);
                shift = be - mu * scale;
            }
            float* o = out + ((size_t)b * Cout + co) * HW + n0 + wn + 2 * q;
#pragma unroll
            for (int j = 0; j < 4; j++) {
                float2 v;
                v.x = acc[i][j][half * 2]     * scale + shift;
                v.y = acc[i][j][half * 2 + 1] * scale + shift;
                *(float2*)&o[j * 8] = v;
            }
        }
}

// =============================================================================
// Dilated 3x3 conv GEMM, tap-outer, bf16x3.  Block: 96M x 128N (one image row).
// K per tap = 96 (pairs padded 43->48).  grid: (H, 1, B), block 256.
// =============================================================================
__global__ __launch_bounds__(256) void dil_mma(
    const u32* __restrict__ wHi, const u32* __restrict__ wLo,   // [9][48][96]
    const u32* __restrict__ aHi, const u32* __restrict__ aLo,   // packed pre
    int basePair, int pairsValid, int dil, int Cg,
    float* __restrict__ out, int coBase, const float* __restrict__ bnp)
{
    __shared__ u32 AsH[8][104], AsL[8][104], BsH[8][136], BsL[8][136];
    const int b    = blockIdx.z;
    const int h    = blockIdx.x;
    const int tid  = threadIdx.x, wid = tid >> 5, lane = tid & 31;
    const int wm   = (wid >> 2) * 48, wn = (wid & 3) * 32;
    const int g    = lane >> 2, q = lane & 3;
    const u32* aHiB = aHi + (size_t)b * 128 * HW;
    const u32* aLoB = aLo + (size_t)b * 128 * HW;

    float acc[3][4][4];
#pragma unroll
    for (int i = 0; i < 3; i++)
#pragma unroll
        for (int j = 0; j < 4; j++)
#pragma unroll
            for (int r = 0; r < 4; r++) acc[i][j][r] = 0.f;

    for (int tap = 0; tap < 9; tap++) {
        const int dy = tap / 3 - 1, dx = tap % 3 - 1;
        const int sh = h + dy * dil;
        const bool rowOk = (sh >= 0 && sh < H_);
        for (int ks = 0; ks < 6; ks++) {
            __syncthreads();
#pragma unroll
            for (int qd = 0; qd < 3; qd++) {
                const int idx = tid + qd * 256;       // < 768
                const int k2 = idx / 96, m = idx - k2 * 96;
                const size_t wo = (size_t)tap * (48 * 96) + (size_t)(ks * 8 + k2) * 96 + m;
                AsH[k2][m] = wHi[wo];  AsL[k2][m] = wLo[wo];
            }
#pragma unroll
            for (int qd = 0; qd < 4; qd++) {
                const int idx = tid + qd * 256;
                const int k2 = idx >> 7, n = idx & 127;
                const int pr = ks * 8 + k2;
                const int s  = n + dx * dil;
                u32 vh = 0, vl = 0;
                if (pr < pairsValid && rowOk && s >= 0 && s < W_) {
                    const size_t ao = (size_t)(basePair + pr) * HW + sh * W_ + s;
                    vh = aHiB[ao];  vl = aLoB[ao];
                }
                BsH[k2][n] = vh;  BsL[k2][n] = vl;
            }
            __syncthreads();

            u32 aH[3][4], aL[3][4], bH[4][2], bL[4][2];
#pragma unroll
            for (int i = 0; i < 3; i++) {
                const int base = wm + i * 16 + g;
                aH[i][0] = AsH[q][base];     aH[i][1] = AsH[q][base + 8];
                aH[i][2] = AsH[q + 4][base]; aH[i][3] = AsH[q + 4][base + 8];
                aL[i][0] = AsL[q][base];     aL[i][1] = AsL[q][base + 8];
                aL[i][2] = AsL[q + 4][base]; aL[i][3] = AsL[q + 4][base + 8];
            }
#pragma unroll
            for (int j = 0; j < 4; j++) {
                const int nb = wn + j * 8 + g;
                bH[j][0] = BsH[q][nb]; bH[j][1] = BsH[q + 4][nb];
                bL[j][0] = BsL[q][nb]; bL[j][1] = BsL[q + 4][nb];
            }
#pragma unroll
            for (int i = 0; i < 3; i++)
#pragma unroll
                for (int j = 0; j < 4; j++) {
                    mma16816(acc[i][j], aH[i], bH[j]);
                    mma16816(acc[i][j], aH[i], bL[j]);
                    mma16816(acc[i][j], aL[i], bH[j]);
                }
        }
    }

#pragma unroll
    for (int i = 0; i < 3; i++)
#pragma unroll
        for (int half = 0; half < 2; half++) {
            const int co = wm + i * 16 + g + half * 8;
            if (co < Cg) {
                const float gg = bnp[co],          be = bnp[Cg + co];
                const float mu = bnp[2 * Cg + co], va = bnp[3 * Cg + co];
                const float scale = gg * rsqrtf(va + 1e-5f);
                const float shift = be - mu * scale;
                float* o = out + ((size_t)b * C_ + coBase + co) * HW + h * W_ + wn + 2 * q;
#pragma unroll
                for (int j = 0; j < 4; j++) {
                    float2 v;
                    v.x = acc[i][j][half * 2]     * scale + shift;
                    v.y = acc[i][j][half * 2 + 1] * scale + shift;
                    *(float2*)&o[j * 8] = v;
                }
            }
        }
}

// =============================================================================
// Windowed attention (unchanged, verified).  grid: (B*256, NH), block 64
// =============================================================================
__global__ __launch_bounds__(64) void attn_kernel(
    const float* __restrict__ qkv, const float* __restrict__ rpb,
    float* __restrict__ out)
{
    const int win  = blockIdx.x;
    const int head = blockIdx.y;
    const int b    = win >> 8;
    const int wy   = (win >> 4) & 15;
    const int wx   = win & 15;
    const int i    = threadIdx.x;
    const int yi   = i >> 3, xi = i & 7;
    const int py   = wy * 8 + yi, px = wx * 8 + xi;

    __shared__ float ks[64][16];
    __shared__ float vs[64][16];
    __shared__ float bias_s[232];

    const size_t pix = (size_t)py * W_ + px;
    const float* qb  = qkv + ((size_t)b * 768 + head * DH) * HW + pix;

    float qv[16];
#pragma unroll
    for (int dd = 0; dd < 16; dd++) {
        qv[dd]    = qb[(size_t)dd * HW];
        ks[i][dd] = qb[(size_t)(256 + dd) * HW];
        vs[i][dd] = qb[(size_t)(512 + dd) * HW];
    }
    for (int t = i; t < 225; t += 64) bias_s[t] = rpb[t * NHD + head];
    __syncthreads();

    float s[64];
    float mx = -1e30f;
#pragma unroll
    for (int j = 0; j < 64; j++) {
        const float4* kr = (const float4*)&ks[j][0];
        float4 k0 = kr[0], k1 = kr[1], k2 = kr[2], k3 = kr[3];
        float dot = qv[0]  * k0.x + qv[1]  * k0.y + qv[2]  * k0.z + qv[3]  * k0.w
                  + qv[4]  * k1.x + qv[5]  * k1.y + qv[6]  * k1.z + qv[7]  * k1.w
                  + qv[8]  * k2.x + qv[9]  * k2.y + qv[10] * k2.z + qv[11] * k2.w
                  + qv[12] * k3.x + qv[13] * k3.y + qv[14] * k3.z + qv[15] * k3.w;
        const int yj = j >> 3, xj = j & 7;
        float val = dot * 0.25f + bias_s[(yi - yj + 7) * 15 + (xi - xj + 7)];
        s[j] = val;
        mx = fmaxf(mx, val);
    }
    float sum = 0.f;
#pragma unroll
    for (int j = 0; j < 64; j++) { float e = __expf(s[j] - mx); s[j] = e; sum += e; }
    const float inv = 1.f / sum;

    float4 o0 = {0, 0, 0, 0}, o1 = o0, o2 = o0, o3 = o0;
#pragma unroll
    for (int j = 0; j < 64; j++) {
        const float p = s[j];
        const float4* vr = (const float4*)&vs[j][0];
        float4 v0 = vr[0], v1 = vr[1], v2 = vr[2], v3 = vr[3];
        o0.x += p * v0.x; o0.y += p * v0.y; o0.z += p * v0.z; o0.w += p * v0.w;
        o1.x += p * v1.x; o1.y += p * v1.y; o1.z += p * v1.z; o1.w += p * v1.w;
        o2.x += p * v2.x; o2.y += p * v2.y; o2.z += p * v2.z; o2.w += p * v2.w;
        o3.x += p * v3.x; o3.y += p * v3.y; o3.z += p * v3.z; o3.w += p * v3.w;
    }

    float ov[16] = {o0.x, o0.y, o0.z, o0.w, o1.x, o1.y, o1.z, o1.w,
                    o2.x, o2.y, o2.z, o2.w, o3.x, o3.y, o3.z, o3.w};
    float* ob = out + ((size_t)b * C_ + head * DH) * HW + pix;
#pragma unroll
    for (int dd = 0; dd < 16; dd++) ob[(size_t)dd * HW] = ov[dd] * inv;
}

// =============================================================================
__global__ __launch_bounds__(256) void pooladd_kernel(
    const float* __restrict__ att, const float* __restrict__ loc,
    float* __restrict__ out)
{
    const size_t idx = (size_t)blockIdx.x * 256 + threadIdx.x;
    const int w = (int)(idx & (W_ - 1));
    const int h = (int)((idx >> 7) & (H_ - 1));
    const size_t bc = idx >> 14;
    const float* p = att + (bc << 14);
    float sx = 0.f, sy = 0.f;
#pragma unroll
    for (int t = -3; t <= 4; t++) {
        const int r = h + t;
        if (r >= 0 && r <= H_) { const int rr = (r == H_) ? H_ - 2 : r; sx += p[rr * W_ + w]; }
        const int c2 = w + t;
        if (c2 >= 0 && c2 <= W_) { const int cc = (c2 == W_) ? W_ - 2 : c2; sy += p[h * W_ + cc]; }
    }
    out[idx] = (sx + sy) * 0.125f + loc[idx];
}

// =============================================================================
__global__ __launch_bounds__(256) void dw_kernel(
    const float* __restrict__ in, const float* __restrict__ wdw,
    float* __restrict__ out)
{
    __shared__ float tile[23][48];
    __shared__ float wt[64];
    const int bc = blockIdx.z;
    const int h0 = blockIdx.y * 16, w0 = blockIdx.x * 16;
    const int tx = threadIdx.x, ty = threadIdx.y;
    const int tid = ty * 16 + tx;
    const float* p = in + (size_t)bc * HW;

    if (tid < 64) wt[tid] = wdw[(size_t)(bc & 255) * 64 + tid];
    for (int t = tid; t < 23 * 23; t += 256) {
        const int r = h0 - 3 + t / 23;
        const int s = w0 - 3 + t % 23;
        float v = 0.f;
        if (r >= 0 && r <= H_ && s >= 0 && s <= W_) {
            const int rr = (r == H_) ? H_ - 2 : r;
            const int ss = (s == W_) ? W_ - 2 : s;
            v = p[rr * W_ + ss];
        }
        tile[t / 23][t % 23] = v;
    }
    __syncthreads();

    float acc = 0.f;
#pragma unroll
    for (int u = 0; u < 8; u++)
#pragma unroll
        for (int v = 0; v < 8; v++)
            acc = fmaf(wt[u * 8 + v], tile[ty + u][tx + v], acc);
    out[(size_t)bc * HW + (h0 + ty) * W_ + w0 + tx] = acc;
}

// =============================================================================
extern "C" void kernel_launch(void* const* d_in, const int* in_sizes, int n_in,
                              void* d_out, int out_size)
{
    const float* x       = (const float*)d_in[0];
    const float* w_pre   = (const float*)d_in[1];
    const float* bn_pre  = (const float*)d_in[2];
    const float* w_l1    = (const float*)d_in[3];
    const float* bn_l1   = (const float*)d_in[4];
    const float* w_l2    = (const float*)d_in[5];
    const float* bn_l2   = (const float*)d_in[6];
    const float* w_l3    = (const float*)d_in[7];
    const float* bn_l3   = (const float*)d_in[8];
    const float* w_qkv   = (const float*)d_in[9];
    const float* rpb     = (const float*)d_in[10];
    const float* w_dw    = (const float*)d_in[11];
    const float* w_pw    = (const float*)d_in[12];
    const float* bn_proj = (const float*)d_in[13];
    float* out = (float*)d_out;

    float *bufA, *bufB, *bufC, *bufD;
    cudaGetSymbolAddress((void**)&bufA, g_bufA);
    cudaGetSymbolAddress((void**)&bufB, g_bufB);
    cudaGetSymbolAddress((void**)&bufC, g_bufC);
    cudaGetSymbolAddress((void**)&bufD, g_bufD);
    u32 *xHi, *xLo, *pHi, *pLo;
    cudaGetSymbolAddress((void**)&xHi, g_xHi);  cudaGetSymbolAddress((void**)&xLo, g_xLo);
    cudaGetSymbolAddress((void**)&pHi, g_pHi);  cudaGetSymbolAddress((void**)&pLo, g_pLo);
    u32 *wPreH, *wPreL, *wQkvH, *wQkvL, *wPwH, *wPwL, *wDilH, *wDilL;
    cudaGetSymbolAddress((void**)&wPreH, g_wPreHi); cudaGetSymbolAddress((void**)&wPreL, g_wPreLo);
    cudaGetSymbolAddress((void**)&wQkvH, g_wQkvHi); cudaGetSymbolAddress((void**)&wQkvL, g_wQkvLo);
    cudaGetSymbolAddress((void**)&wPwH,  g_wPwHi);  cudaGetSymbolAddress((void**)&wPwL,  g_wPwLo);
    cudaGetSymbolAddress((void**)&wDilH, g_wDilHi); cudaGetSymbolAddress((void**)&wDilL, g_wDilLo);

    float* pre  = bufA;
    float* loc  = bufB;
    float* qkvb = bufC;
    float* att  = bufD;
    float* mix  = bufA;
    float* dwo  = bufC;
    u32*   dHi  = pHi;   // stage-7 pack reuses pre-pack buffers (disjoint lifetime)
    u32*   dLo  = pLo;

    const int DW9 = 9 * 48 * 96;
    const int packBlocks = (int)(APACK / 4 / 256);   // 16384

    // ---- weight + input packing ----
    pack_w1x1<<<(256 * 128 + 255) / 256, 256>>>(w_pre, wPreH, wPreL, 256);
    pack_w1x1<<<(768 * 128 + 255) / 256, 256>>>(w_qkv, wQkvH, wQkvL, 768);
    pack_w1x1<<<(256 * 128 + 255) / 256, 256>>>(w_pw,  wPwH,  wPwL,  256);
    pack_wdil<<<(DW9 + 255) / 256, 256>>>(w_l1, wDilH,            wDilL,            86);
    pack_wdil<<<(DW9 + 255) / 256, 256>>>(w_l2, wDilH + DW9,      wDilL + DW9,      86);
    pack_wdil<<<(DW9 + 255) / 256, 256>>>(w_l3, wDilH + 2 * DW9,  wDilL + 2 * DW9,  84);
    pack_act<<<packBlocks, 256>>>(x, xHi, xLo);

    // ---- 1. pre 1x1 + BN ----
    gemm1x1_mma<<<dim3(HW / 128, 2, B_), 256>>>(wPreH, wPreL, 256, xHi, xLo, pre, bn_pre, 256, 1);
    pack_act<<<packBlocks, 256>>>(pre, pHi, pLo);

    // ---- 2. dilated convs + BN ----
    dil_mma<<<dim3(H_, 1, B_), 256>>>(wDilH,           wDilL,           pHi, pLo,  0, 43, 1, 86, loc,   0, bn_l1);
    dil_mma<<<dim3(H_, 1, B_), 256>>>(wDilH + DW9,     wDilL + DW9,     pHi, pLo, 43, 43, 2, 86, loc,  86, bn_l2);
    dil_mma<<<dim3(H_, 1, B_), 256>>>(wDilH + 2 * DW9, wDilL + 2 * DW9, pHi, pLo, 86, 42, 3, 84, loc, 172, bn_l3);

    // ---- 3. qkv 1x1 ----
    gemm1x1_mma<<<dim3(HW / 128, 6, B_), 256>>>(wQkvH, wQkvL, 768, xHi, xLo, qkvb, bn_pre, 768, 0);

    // ---- 4. attention ----
    attn_kernel<<<dim3(B_ * 256, NHD), 64>>>(qkvb, rpb, att);

    // ---- 5. pool + add local ----
    pooladd_kernel<<<dim3((unsigned)((size_t)B_ * C_ * HW / 256)), 256>>>(att, loc, mix);

    // ---- 6. depthwise 8x8 ----
    dw_kernel<<<dim3(8, 8, B_ * C_), dim3(16, 16)>>>(mix, w_dw, dwo);

    // ---- 7. pw 1x1 + BN ----
    pack_act<<<packBlocks, 256>>>(dwo, dHi, dLo);
    gemm1x1_mma<<<dim3(HW / 128, 2, B_), 256>>>(wPwH, wPwL, 256, dHi, dLo, out, bn_proj, 256, 1);
}

// round 7
// speedup vs baseline: 1.9002x; 1.0004x over previous
#include <cuda_runtime.h>
#include <cuda_bf16.h>

typedef unsigned int u32;

#define B_  8
#define C_  256
#define H_  128
#define W_  128
#define HW  16384
#define NHD 16
#define DH  16

// ---------------- fp32 stage buffers (lifetime-aliased) ----------------------
__device__ float g_bufA[(size_t)B_ * C_ * HW];   // pre out  -> mix
__device__ float g_bufB[(size_t)B_ * C_ * HW];   // loc
__device__ float g_bufC[(size_t)B_ * 768 * HW];  // qkv out  -> dwo
__device__ float g_bufD[(size_t)B_ * C_ * HW];   // att

// ------------- packed bf16 (hi,lo) interleaved activations uint2 -------------
#define APACK ((size_t)B_ * 128 * HW)
__device__ uint2 g_xHL[APACK];   // from x       (pre + qkv input)
__device__ uint2 g_pHL[APACK];   // from pre out (dil input), then dwo (pw input)

// ------------- packed bf16 (hi,lo) weights uint2 -----------------------------
// 1x1: [K/2=128][M]; dil: [group][tap 9][pair-row 48][m 128 padded]
__device__ uint2 g_wPreHL[128 * 256];
__device__ uint2 g_wQkvHL[128 * 768];
__device__ uint2 g_wPwHL [128 * 256];
__device__ uint2 g_wDilHL[3 * 9 * 48 * 128];

// ---------------- bf16 split helper ------------------------------------------
__device__ __forceinline__ u32 split_pack(float x0, float x1, u32& lo) {
    __nv_bfloat16 h0 = __float2bfloat16(x0);
    __nv_bfloat16 h1 = __float2bfloat16(x1);
    __nv_bfloat16 l0 = __float2bfloat16(x0 - __bfloat162float(h0));
    __nv_bfloat16 l1 = __float2bfloat16(x1 - __bfloat162float(h1));
    lo = (u32)__bfloat16_as_ushort(l0) | ((u32)__bfloat16_as_ushort(l1) << 16);
    return (u32)__bfloat16_as_ushort(h0) | ((u32)__bfloat16_as_ushort(h1) << 16);
}

// -------- activation pack: fp32 [B][256][HW] -> uint2(hi,lo) [B][128][HW] ----
__global__ __launch_bounds__(256) void pack_act(
    const float* __restrict__ in, uint2* __restrict__ hl)
{
    const size_t idx = (size_t)blockIdx.x * 256 + threadIdx.x; // B*128*(HW/4)
    const size_t p4  = idx & 4095;
    const size_t t   = idx >> 12;              // b*128 + c2
    const int    c2  = (int)(t & 127);
    const int    b   = (int)(t >> 7);
    const float* r0  = in + ((size_t)b * C_ + 2 * c2) * HW + p4 * 4;
    float4 a = *(const float4*)r0;
    float4 c = *(const float4*)(r0 + HW);
    u32 hv[4], lv[4];
    hv[0] = split_pack(a.x, c.x, lv[0]);
    hv[1] = split_pack(a.y, c.y, lv[1]);
    hv[2] = split_pack(a.z, c.z, lv[2]);
    hv[3] = split_pack(a.w, c.w, lv[3]);
    uint2* o = hl + t * HW + p4 * 4;
    *(uint4*)&o[0] = make_uint4(hv[0], lv[0], hv[1], lv[1]);
    *(uint4*)&o[2] = make_uint4(hv[2], lv[2], hv[3], lv[3]);
}

// ---------------- 1x1 weight pack: W[M][256] -> [128][M] ---------------------
__global__ __launch_bounds__(256) void pack_w1x1(
    const float* __restrict__ W, uint2* __restrict__ hl, int M)
{
    const int idx = blockIdx.x * 256 + threadIdx.x;
    if (idx >= M * 128) return;
    const int m = idx % M, k2 = idx / M;
    u32 l;
    u32 h = split_pack(W[m * 256 + 2 * k2], W[m * 256 + 2 * k2 + 1], l);
    hl[(size_t)k2 * M + m] = make_uint2(h, l);
}

// ------------- dil weight pack: W[Cg][Cg][3][3] -> [9][48][128] --------------
__global__ __launch_bounds__(256) void pack_wdil(
    const float* __restrict__ W, uint2* __restrict__ hl, int Cg)
{
    const int idx = blockIdx.x * 256 + threadIdx.x;
    if (idx >= 9 * 48 * 128) return;
    const int m  = idx & 127;
    const int r  = idx >> 7;
    const int k2 = r % 48;
    const int t  = r / 48;
    float a = 0.f, b = 0.f;
    if (m < Cg) {
        if (2 * k2     < Cg) a = W[((size_t)m * Cg + 2 * k2)     * 9 + t];
        if (2 * k2 + 1 < Cg) b = W[((size_t)m * Cg + 2 * k2 + 1) * 9 + t];
    }
    u32 l;
    u32 h = split_pack(a, b, l);
    hl[idx] = make_uint2(h, l);
}

// ---------------- mma.m16n8k16 bf16 wrapper ----------------------------------
__device__ __forceinline__ void mma16816(float* d, const u32* a, const u32* b) {
    asm volatile(
        "mma.sync.aligned.m16n8k16.row.col.f32.bf16.bf16.f32 "
        "{%0,%1,%2,%3}, {%4,%5,%6,%7}, {%8,%9}, {%0,%1,%2,%3};"
        : "+f"(d[0]), "+f"(d[1]), "+f"(d[2]), "+f"(d[3])
        : "r"(a[0]), "r"(a[1]), "r"(a[2]), "r"(a[3]), "r"(b[0]), "r"(b[1]));
}

// =============================================================================
// 1x1 conv GEMM (K=256), bf16x3, double-buffered, LDS.64 fragments.
// Block: 128M x 128N, 8 warps, warp 64x32.  grid: (HW/128, Mtot/128, B).
// =============================================================================
__global__ __launch_bounds__(256) void gemm1x1_mma(
    const uint2* __restrict__ wHL, int Mtot,
    const uint2* __restrict__ aHL,
    float* __restrict__ out, const float* __restrict__ bnp, int Cout, int use_bn)
{
    __shared__ uint2 As[2][8][132];
    __shared__ uint2 Bs[2][8][132];
    const int b    = blockIdx.z;
    const int m0   = blockIdx.y * 128, n0 = blockIdx.x * 128;
    const int tid  = threadIdx.x, wid = tid >> 5, lane = tid & 31;
    const int wm   = (wid >> 2) * 64, wn = (wid & 3) * 32;
    const int g    = lane >> 2, q = lane & 3;
    const uint2* aB = aHL + (size_t)b * 128 * HW + n0;
    const uint2* wB = wHL + m0;

    // loader slot: 512 uint4 per tile, 2 per thread
    const int lk0 = tid >> 6,        lc0 = (tid & 63) * 2;        // slot 0
    const int lk1 = (tid + 256) >> 6, lc1 = lc0;                  // slot 1 (same col, +4 rows)

    float acc[4][4][4];
#pragma unroll
    for (int i = 0; i < 4; i++)
#pragma unroll
        for (int j = 0; j < 4; j++)
#pragma unroll
            for (int r = 0; r < 4; r++) acc[i][j][r] = 0.f;

    uint4 rA0, rA1, rB0, rB1;
    auto loadg = [&](int kk) {
        rA0 = *(const uint4*)&wB[(size_t)(kk * 8 + lk0) * Mtot + lc0];
        rA1 = *(const uint4*)&wB[(size_t)(kk * 8 + lk1) * Mtot + lc1];
        rB0 = *(const uint4*)&aB[(size_t)(kk * 8 + lk0) * HW + lc0];
        rB1 = *(const uint4*)&aB[(size_t)(kk * 8 + lk1) * HW + lc1];
    };
    auto stores = [&](int st) {
        *(uint4*)&As[st][lk0][lc0] = rA0;
        *(uint4*)&As[st][lk1][lc1] = rA1;
        *(uint4*)&Bs[st][lk0][lc0] = rB0;
        *(uint4*)&Bs[st][lk1][lc1] = rB1;
    };

    loadg(0);
    stores(0);
    __syncthreads();

    for (int kk = 0; kk < 16; kk++) {
        const int cur = kk & 1;
        if (kk < 15) loadg(kk + 1);

        uint2 af[4][4], bf[4][2];
#pragma unroll
        for (int i = 0; i < 4; i++) {
            const int base = wm + i * 16 + g;
            af[i][0] = As[cur][q][base];     af[i][1] = As[cur][q][base + 8];
            af[i][2] = As[cur][q + 4][base]; af[i][3] = As[cur][q + 4][base + 8];
        }
#pragma unroll
        for (int j = 0; j < 4; j++) {
            const int nb = wn + j * 8 + g;
            bf[j][0] = Bs[cur][q][nb]; bf[j][1] = Bs[cur][q + 4][nb];
        }
#pragma unroll
        for (int i = 0; i < 4; i++) {
            u32 aH[4] = {af[i][0].x, af[i][1].x, af[i][2].x, af[i][3].x};
            u32 aL[4] = {af[i][0].y, af[i][1].y, af[i][2].y, af[i][3].y};
#pragma unroll
            for (int j = 0; j < 4; j++) {
                u32 bH[2] = {bf[j][0].x, bf[j][1].x};
                u32 bL[2] = {bf[j][0].y, bf[j][1].y};
                mma16816(acc[i][j], aH, bH);
                mma16816(acc[i][j], aH, bL);
                mma16816(acc[i][j], aL, bH);
            }
        }
        if (kk < 15) {
            stores(cur ^ 1);
            __syncthreads();
        }
    }

#pragma unroll
    for (int i = 0; i < 4; i++)
#pragma unroll
        for (int half = 0; half < 2; half++) {
            const int co = m0 + wm + i * 16 + g + half * 8;
            float scale = 1.f, shift = 0.f;
            if (use_bn) {
                const float gg = bnp[co],            be = bnp[Cout + co];
                const float mu = bnp[2 * Cout + co], va = bnp[3 * Cout + co];
                scale = gg * rsqrtf(va + 1e-5f);
                shift = be - mu * scale;
            }
            float* o = out + ((size_t)b * Cout + co) * HW + n0 + wn + 2 * q;
#pragma unroll
            for (int j = 0; j < 4; j++) {
                float2 v;
                v.x = acc[i][j][half * 2]     * scale + shift;
                v.y = acc[i][j][half * 2 + 1] * scale + shift;
                *(float2*)&o[j * 8] = v;
            }
        }
}

// =============================================================================
// Dilated 3x3 conv GEMM, tap-outer, bf16x3, double-buffered.
// Block: 96M x 128N (one image row).  54 pipelined K-steps.
// grid: (H, 1, B), block 256.
// =============================================================================
__global__ __launch_bounds__(256) void dil_mma(
    const uint2* __restrict__ wHL,   // [9][48][128]
    const uint2* __restrict__ aHL,   // packed pre
    int basePair, int pairsValid, int dil, int Cg,
    float* __restrict__ out, int coBase, const float* __restrict__ bnp)
{
    __shared__ uint2 As[2][8][132];
    __shared__ uint2 Bs[2][8][132];
    const int b    = blockIdx.z;
    const int h    = blockIdx.x;
    const int tid  = threadIdx.x, wid = tid >> 5, lane = tid & 31;
    const int wm   = (wid >> 2) * 48, wn = (wid & 3) * 32;
    const int g    = lane >> 2, q = lane & 3;
    const uint2* aB = aHL + (size_t)b * 128 * HW;

    const int lk0 = tid >> 6,         lc0 = (tid & 63) * 2;
    const int lk1 = (tid + 256) >> 6, lc1 = lc0;
    // B loader: 4 uint2 elements per thread
    const int bk0 = tid >> 7,  bn0v = tid & 127;

    float acc[3][4][4];
#pragma unroll
    for (int i = 0; i < 3; i++)
#pragma unroll
        for (int j = 0; j < 4; j++)
#pragma unroll
            for (int r = 0; r < 4; r++) acc[i][j][r] = 0.f;

    uint4 rA0, rA1;
    uint2 rB[4];
    auto loadg = [&](int tap, int ks) {
        const int dy = tap / 3 - 1, dx = tap % 3 - 1;
        const int sh = h + dy * dil;
        const bool rowOk = (sh >= 0 && sh < H_);
        const int rowBase = tap * 48 + ks * 8;
        rA0 = *(const uint4*)&wHL[(size_t)(rowBase + lk0) * 128 + lc0];
        rA1 = *(const uint4*)&wHL[(size_t)(rowBase + lk1) * 128 + lc1];
#pragma unroll
        for (int s = 0; s < 4; s++) {
            const int k2 = bk0 + s * 2;
            const int pr = ks * 8 + k2;
            const int sp = bn0v + dx * dil;
            uint2 v = make_uint2(0u, 0u);
            if (pr < pairsValid && rowOk && sp >= 0 && sp < W_)
                v = aB[(size_t)(basePair + pr) * HW + sh * W_ + sp];
            rB[s] = v;
        }
    };
    auto stores = [&](int st) {
        *(uint4*)&As[st][lk0][lc0] = rA0;
        *(uint4*)&As[st][lk1][lc1] = rA1;
#pragma unroll
        for (int s = 0; s < 4; s++)
            Bs[st][bk0 + s * 2][bn0v] = rB[s];
    };

    loadg(0, 0);
    stores(0);
    __syncthreads();

    int tap = 0, ks = 0;
    for (int step = 0; step < 54; step++) {
        const int cur = step & 1;
        const int ntap = (ks == 5) ? tap + 1 : tap;
        const int nks  = (ks == 5) ? 0 : ks + 1;
        if (step < 53) loadg(ntap, nks);

        uint2 af[3][4], bf[4][2];
#pragma unroll
        for (int i = 0; i < 3; i++) {
            const int base = wm + i * 16 + g;
            af[i][0] = As[cur][q][base];     af[i][1] = As[cur][q][base + 8];
            af[i][2] = As[cur][q + 4][base]; af[i][3] = As[cur][q + 4][base + 8];
        }
#pragma unroll
        for (int j = 0; j < 4; j++) {
            const int nb = wn + j * 8 + g;
            bf[j][0] = Bs[cur][q][nb]; bf[j][1] = Bs[cur][q + 4][nb];
        }
#pragma unroll
        for (int i = 0; i < 3; i++) {
            u32 aH[4] = {af[i][0].x, af[i][1].x, af[i][2].x, af[i][3].x};
            u32 aL[4] = {af[i][0].y, af[i][1].y, af[i][2].y, af[i][3].y};
#pragma unroll
            for (int j = 0; j < 4; j++) {
                u32 bH[2] = {bf[j][0].x, bf[j][1].x};
                u32 bL[2] = {bf[j][0].y, bf[j][1].y};
                mma16816(acc[i][j], aH, bH);
                mma16816(acc[i][j], aH, bL);
                mma16816(acc[i][j], aL, bH);
            }
        }
        if (step < 53) {
            stores(cur ^ 1);
            __syncthreads();
        }
        tap = ntap; ks = nks;
    }

#pragma unroll
    for (int i = 0; i < 3; i++)
#pragma unroll
        for (int half = 0; half < 2; half++) {
            const int co = wm + i * 16 + g + half * 8;
            if (co < Cg) {
                const float gg = bnp[co],          be = bnp[Cg + co];
                const float mu = bnp[2 * Cg + co], va = bnp[3 * Cg + co];
                const float scale = gg * rsqrtf(va + 1e-5f);
                const float shift = be - mu * scale;
                float* o = out + ((size_t)b * C_ + coBase + co) * HW + h * W_ + wn + 2 * q;
#pragma unroll
                for (int j = 0; j < 4; j++) {
                    float2 v;
                    v.x = acc[i][j][half * 2]     * scale + shift;
                    v.y = acc[i][j][half * 2 + 1] * scale + shift;
                    *(float2*)&o[j * 8] = v;
                }
            }
        }
}

// =============================================================================
// Windowed attention (unchanged, verified).  grid: (B*256, NH), block 64
// =============================================================================
__global__ __launch_bounds__(64) void attn_kernel(
    const float* __restrict__ qkv, const float* __restrict__ rpb,
    float* __restrict__ out)
{
    const int win  = blockIdx.x;
    const int head = blockIdx.y;
    const int b    = win >> 8;
    const int wy   = (win >> 4) & 15;
    const int wx   = win & 15;
    const int i    = threadIdx.x;
    const int yi   = i >> 3, xi = i & 7;
    const int py   = wy * 8 + yi, px = wx * 8 + xi;

    __shared__ float ks[64][16];
    __shared__ float vs[64][16];
    __shared__ float bias_s[232];

    const size_t pix = (size_t)py * W_ + px;
    const float* qb  = qkv + ((size_t)b * 768 + head * DH) * HW + pix;

    float qv[16];
#pragma unroll
    for (int dd = 0; dd < 16; dd++) {
        qv[dd]    = qb[(size_t)dd * HW];
        ks[i][dd] = qb[(size_t)(256 + dd) * HW];
        vs[i][dd] = qb[(size_t)(512 + dd) * HW];
    }
    for (int t = i; t < 225; t += 64) bias_s[t] = rpb[t * NHD + head];
    __syncthreads();

    float s[64];
    float mx = -1e30f;
#pragma unroll
    for (int j = 0; j < 64; j++) {
        const float4* kr = (const float4*)&ks[j][0];
        float4 k0 = kr[0], k1 = kr[1], k2 = kr[2], k3 = kr[3];
        float dot = qv[0]  * k0.x + qv[1]  * k0.y + qv[2]  * k0.z + qv[3]  * k0.w
                  + qv[4]  * k1.x + qv[5]  * k1.y + qv[6]  * k1.z + qv[7]  * k1.w
                  + qv[8]  * k2.x + qv[9]  * k2.y + qv[10] * k2.z + qv[11] * k2.w
                  + qv[12] * k3.x + qv[13] * k3.y + qv[14] * k3.z + qv[15] * k3.w;
        const int yj = j >> 3, xj = j & 7;
        float val = dot * 0.25f + bias_s[(yi - yj + 7) * 15 + (xi - xj + 7)];
        s[j] = val;
        mx = fmaxf(mx, val);
    }
    float sum = 0.f;
#pragma unroll
    for (int j = 0; j < 64; j++) { float e = __expf(s[j] - mx); s[j] = e; sum += e; }
    const float inv = 1.f / sum;

    float4 o0 = {0, 0, 0, 0}, o1 = o0, o2 = o0, o3 = o0;
#pragma unroll
    for (int j = 0; j < 64; j++) {
        const float p = s[j];
        const float4* vr = (const float4*)&vs[j][0];
        float4 v0 = vr[0], v1 = vr[1], v2 = vr[2], v3 = vr[3];
        o0.x += p * v0.x; o0.y += p * v0.y; o0.z += p * v0.z; o0.w += p * v0.w;
        o1.x += p * v1.x; o1.y += p * v1.y; o1.z += p * v1.z; o1.w += p * v1.w;
        o2.x += p * v2.x; o2.y += p * v2.y; o2.z += p * v2.z; o2.w += p * v2.w;
        o3.x += p * v3.x; o3.y += p * v3.y; o3.z += p * v3.z; o3.w += p * v3.w;
    }

    float ov[16] = {o0.x, o0.y, o0.z, o0.w, o1.x, o1.y, o1.z, o1.w,
                    o2.x, o2.y, o2.z, o2.w, o3.x, o3.y, o3.z, o3.w};
    float* ob = out + ((size_t)b * C_ + head * DH) * HW + pix;
#pragma unroll
    for (int dd = 0; dd < 16; dd++) ob[(size_t)dd * HW] = ov[dd] * inv;
}

// =============================================================================
__global__ __launch_bounds__(256) void pooladd_kernel(
    const float* __restrict__ att, const float* __restrict__ loc,
    float* __restrict__ out)
{
    const size_t idx = (size_t)blockIdx.x * 256 + threadIdx.x;
    const int w = (int)(idx & (W_ - 1));
    const int h = (int)((idx >> 7) & (H_ - 1));
    const size_t bc = idx >> 14;
    const float* p = att + (bc << 14);
    float sx = 0.f, sy = 0.f;
#pragma unroll
    for (int t = -3; t <= 4; t++) {
        const int r = h + t;
        if (r >= 0 && r <= H_) { const int rr = (r == H_) ? H_ - 2 : r; sx += p[rr * W_ + w]; }
        const int c2 = w + t;
        if (c2 >= 0 && c2 <= W_) { const int cc = (c2 == W_) ? W_ - 2 : c2; sy += p[h * W_ + cc]; }
    }
    out[idx] = (sx + sy) * 0.125f + loc[idx];
}

// =============================================================================
__global__ __launch_bounds__(256) void dw_kernel(
    const float* __restrict__ in, const float* __restrict__ wdw,
    float* __restrict__ out)
{
    __shared__ float tile[23][48];
    __shared__ float wt[64];
    const int bc = blockIdx.z;
    const int h0 = blockIdx.y * 16, w0 = blockIdx.x * 16;
    const int tx = threadIdx.x, ty = threadIdx.y;
    const int tid = ty * 16 + tx;
    const float* p = in + (size_t)bc * HW;

    if (tid < 64) wt[tid] = wdw[(size_t)(bc & 255) * 64 + tid];
    for (int t = tid; t < 23 * 23; t += 256) {
        const int r = h0 - 3 + t / 23;
        const int s = w0 - 3 + t % 23;
        float v = 0.f;
        if (r >= 0 && r <= H_ && s >= 0 && s <= W_) {
            const int rr = (r == H_) ? H_ - 2 : r;
            const int ss = (s == W_) ? W_ - 2 : s;
            v = p[rr * W_ + ss];
        }
        tile[t / 23][t % 23] = v;
    }
    __syncthreads();

    float acc = 0.f;
#pragma unroll
    for (int u = 0; u < 8; u++)
#pragma unroll
        for (int v = 0; v < 8; v++)
            acc = fmaf(wt[u * 8 + v], tile[ty + u][tx + v], acc);
    out[(size_t)bc * HW + (h0 + ty) * W_ + w0 + tx] = acc;
}

// =============================================================================
extern "C" void kernel_launch(void* const* d_in, const int* in_sizes, int n_in,
                              void* d_out, int out_size)
{
    const float* x       = (const float*)d_in[0];
    const float* w_pre   = (const float*)d_in[1];
    const float* bn_pre  = (const float*)d_in[2];
    const float* w_l1    = (const float*)d_in[3];
    const float* bn_l1   = (const float*)d_in[4];
    const float* w_l2    = (const float*)d_in[5];
    const float* bn_l2   = (const float*)d_in[6];
    const float* w_l3    = (const float*)d_in[7];
    const float* bn_l3   = (const float*)d_in[8];
    const float* w_qkv   = (const float*)d_in[9];
    const float* rpb     = (const float*)d_in[10];
    const float* w_dw    = (const float*)d_in[11];
    const float* w_pw    = (const float*)d_in[12];
    const float* bn_proj = (const float*)d_in[13];
    float* out = (float*)d_out;

    float *bufA, *bufB, *bufC, *bufD;
    cudaGetSymbolAddress((void**)&bufA, g_bufA);
    cudaGetSymbolAddress((void**)&bufB, g_bufB);
    cudaGetSymbolAddress((void**)&bufC, g_bufC);
    cudaGetSymbolAddress((void**)&bufD, g_bufD);
    uint2 *xHL, *pHL, *wPre, *wQkv, *wPw, *wDil;
    cudaGetSymbolAddress((void**)&xHL,  g_xHL);
    cudaGetSymbolAddress((void**)&pHL,  g_pHL);
    cudaGetSymbolAddress((void**)&wPre, g_wPreHL);
    cudaGetSymbolAddress((void**)&wQkv, g_wQkvHL);
    cudaGetSymbolAddress((void**)&wPw,  g_wPwHL);
    cudaGetSymbolAddress((void**)&wDil, g_wDilHL);

    float* pre  = bufA;
    float* loc  = bufB;
    float* qkvb = bufC;
    float* att  = bufD;
    float* mix  = bufA;
    float* dwo  = bufC;
    uint2* dHL  = pHL;   // stage-7 pack reuses pre-pack buffer (disjoint lifetime)

    const int DW = 9 * 48 * 128;
    const int packBlocks = (int)(APACK / 4 / 256);   // 16384

    // ---- weight + input packing ----
    pack_w1x1<<<(256 * 128 + 255) / 256, 256>>>(w_pre, wPre, 256);
    pack_w1x1<<<(768 * 128 + 255) / 256, 256>>>(w_qkv, wQkv, 768);
    pack_w1x1<<<(256 * 128 + 255) / 256, 256>>>(w_pw,  wPw,  256);
    pack_wdil<<<(DW + 255) / 256, 256>>>(w_l1, wDil,          86);
    pack_wdil<<<(DW + 255) / 256, 256>>>(w_l2, wDil + DW,     86);
    pack_wdil<<<(DW + 255) / 256, 256>>>(w_l3, wDil + 2 * DW, 84);
    pack_act<<<packBlocks, 256>>>(x, xHL);

    // ---- 1. pre 1x1 + BN ----
    gemm1x1_mma<<<dim3(HW / 128, 2, B_), 256>>>(wPre, 256, xHL, pre, bn_pre, 256, 1);
    pack_act<<<packBlocks, 256>>>(pre, pHL);

    // ---- 2. dilated convs + BN ----
    dil_mma<<<dim3(H_, 1, B_), 256>>>(wDil,          pHL,  0, 43, 1, 86, loc,   0, bn_l1);
    dil_mma<<<dim3(H_, 1, B_), 256>>>(wDil + DW,     pHL, 43, 43, 2, 86, loc,  86, bn_l2);
    dil_mma<<<dim3(H_, 1, B_), 256>>>(wDil + 2 * DW, pHL, 86, 42, 3, 84, loc, 172, bn_l3);

    // ---- 3. qkv 1x1 ----
    gemm1x1_mma<<<dim3(HW / 128, 6, B_), 256>>>(wQkv, 768, xHL, qkvb, bn_pre, 768, 0);

    // ---- 4. attention ----
    attn_kernel<<<dim3(B_ * 256, NHD), 64>>>(qkvb, rpb, att);

    // ---- 5. pool + add local ----
    pooladd_kernel<<<dim3((unsigned)((size_t)B_ * C_ * HW / 256)), 256>>>(att, loc, mix);

    // ---- 6. depthwise 8x8 ----
    dw_kernel<<<dim3(8, 8, B_ * C_), dim3(16, 16)>>>(mix, w_dw, dwo);

    // ---- 7. pw 1x1 + BN ----
    pack_act<<<packBlocks, 256>>>(dwo, dHL);
    gemm1x1_mma<<<dim3(HW / 128, 2, B_), 256>>>(wPw, 256, dHL, out, bn_proj, 256, 1);
}